// round 8
// baseline (speedup 1.0000x reference)
#include <cuda_runtime.h>
#include <cuda_bf16.h>
#include <cuda_fp16.h>
#include <cooperative_groups.h>
#include <cstdint>

namespace cg = cooperative_groups;

// LightGCN as a single cooperative megakernel (7 phases, 6 grid.sync()s).
// deg = clamp(segsum(w by dst), 1); norm = deg^-1/2
// repeat 2x: h = segsum((h*norm)[src] * w, by dst) * norm
// out = mean(h0, h1, h2)

#define NN   100000
#define EE   1600000
#define SB   512                      // nodes per scan block
#define NBLK ((NN + SB - 1) / SB)     // 196

__device__ float   g_deg[NN];
__device__ int     g_cnt[NN];
__device__ float   g_norm[NN];
__device__ int     g_rowptr[NN + 1];
__device__ int     g_rank[EE];               // edge's slot within its dst bucket
__device__ int     g_bsum[NBLK];
__device__ float2  g_edge[EE];               // .x = bits(src), .y = w
__device__ __half2 g_ha[(size_t)NN * 32];    // layer-1 input (h0*norm)
__device__ __half2 g_hb[(size_t)NN * 32];    // layer-2 input (h1*norm)

// Warp-per-node gather. Lane owns dims [2*lane, 2*lane+1].
// LAYER=0: read g_ha; g_hb = fp16(sum * norm^2).
// LAYER=1: read g_hb; out = (h0 + hb_own/norm + sum*norm) / 3.
template <int LAYER>
__device__ __forceinline__ void gather_phase(const float2* __restrict__ h2,
                                             float2* __restrict__ out,
                                             int n, int warp_id, int nwarps,
                                             int lane) {
    const __half2* hin = (LAYER == 0) ? g_ha : g_hb;
    for (int node = warp_id; node < n; node += nwarps) {
        int beg = g_rowptr[node];
        int end = g_rowptr[node + 1];
        float ax = 0.f, ay = 0.f;
        int j = beg;
        for (; j + 4 <= end; j += 4) {
            float2 e0 = g_edge[j],   e1 = g_edge[j + 1];
            float2 e2 = g_edge[j + 2], e3 = g_edge[j + 3];
            float2 v0 = __half22float2(hin[(size_t)__float_as_int(e0.x) * 32 + lane]);
            float2 v1 = __half22float2(hin[(size_t)__float_as_int(e1.x) * 32 + lane]);
            float2 v2 = __half22float2(hin[(size_t)__float_as_int(e2.x) * 32 + lane]);
            float2 v3 = __half22float2(hin[(size_t)__float_as_int(e3.x) * 32 + lane]);
            ax += v0.x * e0.y; ay += v0.y * e0.y;
            ax += v1.x * e1.y; ay += v1.y * e1.y;
            ax += v2.x * e2.y; ay += v2.y * e2.y;
            ax += v3.x * e3.y; ay += v3.y * e3.y;
        }
        for (; j < end; ++j) {
            float2 e = g_edge[j];
            float2 v = __half22float2(hin[(size_t)__float_as_int(e.x) * 32 + lane]);
            ax += v.x * e.y; ay += v.y * e.y;
        }
        float nm = g_norm[node];
        size_t idx = (size_t)node * 32 + lane;
        if (LAYER == 0) {
            float nm2 = nm * nm;                 // h1*norm = sum*norm^2
            g_hb[idx] = __floats2half2_rn(ax * nm2, ay * nm2);
        } else {
            float hx2 = ax * nm, hy2 = ay * nm;  // h2
            float rin = __frcp_rn(nm);           // 1/norm  (norm in (0,1])
            float2 hbv = __half22float2(g_hb[idx]);
            float h1x = hbv.x * rin, h1y = hbv.y * rin;
            float2 h0 = h2[idx];
            const float third = 1.0f / 3.0f;
            out[idx] = make_float2((h0.x + h1x + hx2) * third,
                                   (h0.y + h1y + hy2) * third);
        }
    }
}

__global__ void __launch_bounds__(SB, 2)
lightgcn_mega(const float4* __restrict__ h4, const float2* __restrict__ h2,
              const float* __restrict__ w, const int* __restrict__ src,
              const int* __restrict__ dst, float2* __restrict__ out,
              int n, int e) {
    cg::grid_group grid = cg::this_grid();
    __shared__ int sh[SB / 32];
    __shared__ int s_off;

    const int tid   = threadIdx.x;
    const int lane  = tid & 31;
    const int wid   = tid >> 5;
    const int gtid  = blockIdx.x * SB + tid;
    const int gsize = gridDim.x * SB;

    // P0: zero deg/cnt
    for (int i = gtid; i < n; i += gsize) { g_deg[i] = 0.0f; g_cnt[i] = 0; }
    grid.sync();

    // P1: weighted degree + per-edge rank within dst bucket
    for (int i = gtid; i < e; i += gsize) {
        int d = dst[i];
        atomicAdd(&g_deg[d], w[i]);
        g_rank[i] = atomicAdd(&g_cnt[d], 1);
    }
    grid.sync();

    // P2: per-node-block exclusive scan of cnt -> rowptr (local); totals -> bsum
    for (int nb = blockIdx.x; nb < NBLK; nb += gridDim.x) {
        int i = nb * SB + tid;
        int v = (i < n) ? g_cnt[i] : 0;
        int x = v;
        #pragma unroll
        for (int o = 1; o < 32; o <<= 1) {
            int y = __shfl_up_sync(0xffffffffu, x, o);
            if (lane >= o) x += y;
        }
        if (lane == 31) sh[wid] = x;
        __syncthreads();
        if (tid == 0) {
            int acc = 0;
            #pragma unroll
            for (int k = 0; k < SB / 32; k++) { int t = sh[k]; sh[k] = acc; acc += t; }
            g_bsum[nb] = acc;
        }
        __syncthreads();
        if (i < n) g_rowptr[i] = x - v + sh[wid];
        __syncthreads();
    }
    grid.sync();

    // P3: add block offsets; compute norm
    for (int nb = blockIdx.x; nb < NBLK; nb += gridDim.x) {
        if (tid < 32) {
            int acc = 0;
            for (int k = lane; k < nb; k += 32) acc += g_bsum[k];
            #pragma unroll
            for (int o = 16; o > 0; o >>= 1)
                acc += __shfl_down_sync(0xffffffffu, acc, o);
            if (lane == 0) s_off = acc;
        }
        __syncthreads();
        int i = nb * SB + tid;
        if (i < n) {
            g_rowptr[i] += s_off;
            g_norm[i] = rsqrtf(fmaxf(g_deg[i], 1.0f));
        }
        __syncthreads();
    }
    if (gtid == 0) g_rowptr[n] = e;
    grid.sync();

    // P4: fill CSR (atomic-free) + prep g_ha = fp16(h0 * norm)
    for (int i = gtid; i < e; i += gsize) {
        int d = dst[i];
        g_edge[g_rowptr[d] + g_rank[i]] = make_float2(__int_as_float(src[i]), w[i]);
    }
    const int n16 = n * 16;
    for (int idx4 = gtid; idx4 < n16; idx4 += gsize) {
        int node = idx4 >> 4;
        float nm = g_norm[node];
        float4 v = h4[idx4];
        g_ha[(size_t)idx4 * 2]     = __floats2half2_rn(v.x * nm, v.y * nm);
        g_ha[(size_t)idx4 * 2 + 1] = __floats2half2_rn(v.z * nm, v.w * nm);
    }
    grid.sync();

    // P5 / P6: the two propagation layers
    const int warp_id = blockIdx.x * (SB / 32) + wid;
    const int nwarps  = gridDim.x * (SB / 32);
    gather_phase<0>(h2, out, n, warp_id, nwarps, lane);
    grid.sync();
    gather_phase<1>(h2, out, n, warp_id, nwarps, lane);
}

extern "C" void kernel_launch(void* const* d_in, const int* in_sizes, int n_in,
                              void* d_out, int out_size) {
    const float4* h4  = (const float4*)d_in[0];
    const float2* h2  = (const float2*)d_in[0];
    const float*  w   = (const float*)d_in[1];
    const int*    src = (const int*)d_in[2];
    const int*    dst = (const int*)d_in[3];
    float2* out = (float2*)d_out;

    int n = in_sizes[0] / 64;   // 100000
    int e = in_sizes[1];        // 1600000

    int dev = 0;
    cudaGetDevice(&dev);
    int sms = 148;
    cudaDeviceGetAttribute(&sms, cudaDevAttrMultiProcessorCount, dev);
    int occ = 2;
    cudaOccupancyMaxActiveBlocksPerMultiprocessor(&occ, lightgcn_mega, SB, 0);
    if (occ < 1) occ = 1;
    int blocks = sms * occ;

    void* args[] = { (void*)&h4, (void*)&h2, (void*)&w, (void*)&src,
                     (void*)&dst, (void*)&out, (void*)&n, (void*)&e };
    cudaLaunchCooperativeKernel((void*)lightgcn_mega, dim3(blocks), dim3(SB),
                                args, 0, 0);
}

// round 9
// speedup vs baseline: 1.7787x; 1.7787x over previous
#include <cuda_runtime.h>
#include <cuda_bf16.h>
#include <cuda_fp16.h>
#include <cstdint>

// LightGCN via pull-based CSR gather, fp16 intermediate embeddings.
// deg = clamp(segsum(w by dst), 1); norm = deg^-1/2
// repeat 2x: h = segsum((h*norm)[src] * w, by dst) * norm
// out = mean(h0, h1, h2) -- assembled in the final gather.

#define NN     100000
#define EE     1600000
#define SCAN_B 256
#define NB_MAX 512                       // >= ceil(NN/SCAN_B) = 391

__device__ float   g_deg[NN];
__device__ int     g_cnt[NN];
__device__ float   g_norm[NN];
__device__ int     g_rowptr[NN + 1];
__device__ int     g_rank[EE];               // edge slot within its dst bucket
__device__ int     g_bsum[NB_MAX];
__device__ float2  g_edge[EE];               // .x = bits(src), .y = w
__device__ __half2 g_ha[(size_t)NN * 32];    // layer-1 input (h0*norm)
__device__ __half2 g_hb[(size_t)NN * 32];    // layer-2 input (h1*norm)

// ---------------- CSR build ----------------

// weighted degree (no-return red) + per-edge rank (atomic return)
__global__ void k_hist(const float* __restrict__ w,
                       const int* __restrict__ dst, int e) {
    int i = blockIdx.x * blockDim.x + threadIdx.x;
    if (i >= e) return;
    int d = dst[i];
    asm volatile("red.global.add.f32 [%0], %1;"
                 :: "l"(&g_deg[d]), "f"(w[i]) : "memory");
    g_rank[i] = atomicAdd(&g_cnt[d], 1);
}

// per-block (256-node) exclusive scan of cnt -> rowptr(local); totals -> bsum
__global__ void k_scanA(int n) {
    __shared__ int sh[8];
    int i = blockIdx.x * SCAN_B + threadIdx.x;
    int lane = threadIdx.x & 31, wid = threadIdx.x >> 5;
    int v = (i < n) ? g_cnt[i] : 0;
    int x = v;
    #pragma unroll
    for (int o = 1; o < 32; o <<= 1) {
        int y = __shfl_up_sync(0xffffffffu, x, o);
        if (lane >= o) x += y;
    }
    if (lane == 31) sh[wid] = x;
    __syncthreads();
    if (threadIdx.x == 0) {
        int acc = 0;
        #pragma unroll
        for (int k = 0; k < 8; k++) { int t = sh[k]; sh[k] = acc; acc += t; }
        g_bsum[blockIdx.x] = acc;
    }
    __syncthreads();
    int excl = x - v + sh[wid];
    if (i < n) g_rowptr[i] = excl;
}

// finalize rowptr (+block offset) and compute norm. No prep here.
__global__ void k_scanC(int n, int e) {
    __shared__ int s_off;
    int t = threadIdx.x;
    int lane = t & 31;
    if (t < 32) {
        int acc = 0;
        for (int k = lane; k < blockIdx.x; k += 32) acc += g_bsum[k];
        #pragma unroll
        for (int o = 16; o > 0; o >>= 1)
            acc += __shfl_down_sync(0xffffffffu, acc, o);
        if (lane == 0) s_off = acc;
    }
    __syncthreads();
    int i = blockIdx.x * SCAN_B + t;
    if (i < n) {
        g_rowptr[i] += s_off;
        g_norm[i] = rsqrtf(fmaxf(g_deg[i], 1.0f));
        if (i == 0) g_rowptr[n] = e;
    }
}

// pure streaming prep: g_ha = fp16(h0 * norm). One float4 per thread.
__global__ void k_prep(const float4* __restrict__ h, int n16) {
    int idx4 = blockIdx.x * blockDim.x + threadIdx.x;
    if (idx4 >= n16) return;
    float nm = __ldg(&g_norm[idx4 >> 4]);
    float4 v = h[idx4];
    g_ha[(size_t)idx4 * 2]     = __floats2half2_rn(v.x * nm, v.y * nm);
    g_ha[(size_t)idx4 * 2 + 1] = __floats2half2_rn(v.z * nm, v.w * nm);
}

// atomic-free CSR fill via precomputed rank
__global__ void k_fill(const int* __restrict__ src,
                       const int* __restrict__ dst,
                       const float* __restrict__ w, int e) {
    int i = blockIdx.x * blockDim.x + threadIdx.x;
    if (i >= e) return;
    int pos = g_rowptr[dst[i]] + g_rank[i];
    g_edge[pos] = make_float2(__int_as_float(src[i]), w[i]);
}

// ---------------- gather layers ----------------

// Warp per node; lane owns dims [2*lane, 2*lane+1] (one __half2).
// LAYER=0: read g_ha; g_hb = fp16(sum * norm^2). No out access.
// LAYER=1: read g_hb; out = (h0 + hb_own/norm + sum*norm) / 3.
template <int LAYER>
__global__ void k_gather(const float2* __restrict__ h2,
                         float2* __restrict__ out, int n) {
    const __half2* hin = (LAYER == 0) ? g_ha : g_hb;
    int warp = (blockIdx.x * blockDim.x + threadIdx.x) >> 5;
    int lane = threadIdx.x & 31;
    if (warp >= n) return;
    int beg = g_rowptr[warp];
    int end = g_rowptr[warp + 1];

    float ax = 0.f, ay = 0.f;
    int j = beg;
    for (; j + 8 <= end; j += 8) {
        float2 e0 = g_edge[j],   e1 = g_edge[j+1];
        float2 e2 = g_edge[j+2], e3 = g_edge[j+3];
        float2 e4 = g_edge[j+4], e5 = g_edge[j+5];
        float2 e6 = g_edge[j+6], e7 = g_edge[j+7];
        float2 v0 = __half22float2(hin[(size_t)__float_as_int(e0.x) * 32 + lane]);
        float2 v1 = __half22float2(hin[(size_t)__float_as_int(e1.x) * 32 + lane]);
        float2 v2 = __half22float2(hin[(size_t)__float_as_int(e2.x) * 32 + lane]);
        float2 v3 = __half22float2(hin[(size_t)__float_as_int(e3.x) * 32 + lane]);
        float2 v4 = __half22float2(hin[(size_t)__float_as_int(e4.x) * 32 + lane]);
        float2 v5 = __half22float2(hin[(size_t)__float_as_int(e5.x) * 32 + lane]);
        float2 v6 = __half22float2(hin[(size_t)__float_as_int(e6.x) * 32 + lane]);
        float2 v7 = __half22float2(hin[(size_t)__float_as_int(e7.x) * 32 + lane]);
        ax += v0.x * e0.y; ay += v0.y * e0.y;
        ax += v1.x * e1.y; ay += v1.y * e1.y;
        ax += v2.x * e2.y; ay += v2.y * e2.y;
        ax += v3.x * e3.y; ay += v3.y * e3.y;
        ax += v4.x * e4.y; ay += v4.y * e4.y;
        ax += v5.x * e5.y; ay += v5.y * e5.y;
        ax += v6.x * e6.y; ay += v6.y * e6.y;
        ax += v7.x * e7.y; ay += v7.y * e7.y;
    }
    for (; j < end; ++j) {
        float2 e = g_edge[j];
        float2 v = __half22float2(hin[(size_t)__float_as_int(e.x) * 32 + lane]);
        ax += v.x * e.y; ay += v.y * e.y;
    }

    float nm = g_norm[warp];
    size_t idx = (size_t)warp * 32 + lane;
    if (LAYER == 0) {
        float nm2 = nm * nm;
        g_hb[idx] = __floats2half2_rn(ax * nm2, ay * nm2);
    } else {
        float hx2 = ax * nm, hy2 = ay * nm;
        float rin = __frcp_rn(nm);
        float2 hbv = __half22float2(g_hb[idx]);
        float h1x = hbv.x * rin, h1y = hbv.y * rin;
        float2 h0 = h2[idx];
        const float third = 1.0f / 3.0f;
        out[idx] = make_float2((h0.x + h1x + hx2) * third,
                               (h0.y + h1y + hy2) * third);
    }
}

extern "C" void kernel_launch(void* const* d_in, const int* in_sizes, int n_in,
                              void* d_out, int out_size) {
    const float* h   = (const float*)d_in[0];
    const float* w   = (const float*)d_in[1];
    const int*   src = (const int*)d_in[2];
    const int*   dst = (const int*)d_in[3];
    float* out = (float*)d_out;

    const int N  = in_sizes[0] / 64;   // 100000
    const int E  = in_sizes[1];        // 1600000
    const int B  = 256;
    const int nb = (N + SCAN_B - 1) / SCAN_B;   // 391
    const int N16 = N * 16;

    // zero deg/cnt via memset nodes (graph-capturable, no allocation)
    void* p_deg = nullptr; void* p_cnt = nullptr;
    cudaGetSymbolAddress(&p_deg, g_deg);
    cudaGetSymbolAddress(&p_cnt, g_cnt);
    cudaMemsetAsync(p_deg, 0, NN * sizeof(float));
    cudaMemsetAsync(p_cnt, 0, NN * sizeof(int));

    k_hist <<<(E + B - 1) / B, B>>>(w, dst, E);
    k_scanA<<<nb, SCAN_B>>>(N);
    k_scanC<<<nb, SCAN_B>>>(N, E);
    k_prep <<<(N16 + B - 1) / B, B>>>((const float4*)h, N16);
    k_fill <<<(E + B - 1) / B, B>>>(src, dst, w, E);

    const int grid = (N + (B / 32) - 1) / (B / 32);
    k_gather<0><<<grid, B>>>((const float2*)h, (float2*)out, N);
    k_gather<1><<<grid, B>>>((const float2*)h, (float2*)out, N);
}

// round 10
// speedup vs baseline: 2.3467x; 1.3194x over previous
#include <cuda_runtime.h>
#include <cuda_bf16.h>
#include <cuda_fp16.h>
#include <cstdint>

// LightGCN via pull-based CSR gather, fp16 intermediate embeddings.
// deg = clamp(segsum(w by dst), 1); norm = deg^-1/2
// repeat 2x: h = segsum((h*norm)[src] * w, by dst) * norm
// out = mean(h0, h1, h2) -- assembled in the final gather.
//
// Gather: 8 lanes per node (lane = 16B of the 128B fp16 row) -> 4 nodes/warp,
// 16 outstanding row loads per warp at unroll-4 (latency hiding).

#define NN     100000
#define EE     1600000
#define SCAN_B 256
#define NB_MAX 512                       // >= ceil(NN/SCAN_B) = 391

__device__ float   g_deg[NN];            // zero at module load; re-zeroed each launch
__device__ int     g_cnt[NN];            // "
__device__ float   g_norm[NN];
__device__ int     g_rowptr[NN + 1];
__device__ int     g_rank[EE];           // edge slot within its dst bucket
__device__ int     g_bsum[NB_MAX];
__device__ float2  g_edge[EE];           // .x = bits(src), .y = w
__device__ uint4   g_ha[(size_t)NN * 8]; // layer-1 input (h0*norm), fp16, 8x16B/row
__device__ uint4   g_hb[(size_t)NN * 8]; // layer-2 input (h1*norm), fp16

// ---------------- CSR build ----------------

// weighted degree (no-return red) + per-edge rank (atomic return)
__global__ void k_hist(const float* __restrict__ w,
                       const int* __restrict__ dst, int e) {
    int i = blockIdx.x * blockDim.x + threadIdx.x;
    if (i >= e) return;
    int d = dst[i];
    asm volatile("red.global.add.f32 [%0], %1;"
                 :: "l"(&g_deg[d]), "f"(w[i]) : "memory");
    g_rank[i] = atomicAdd(&g_cnt[d], 1);
}

// per-block (256-node) exclusive scan of cnt -> rowptr(local); totals -> bsum
__global__ void k_scanA(int n) {
    __shared__ int sh[8];
    int i = blockIdx.x * SCAN_B + threadIdx.x;
    int lane = threadIdx.x & 31, wid = threadIdx.x >> 5;
    int v = (i < n) ? g_cnt[i] : 0;
    int x = v;
    #pragma unroll
    for (int o = 1; o < 32; o <<= 1) {
        int y = __shfl_up_sync(0xffffffffu, x, o);
        if (lane >= o) x += y;
    }
    if (lane == 31) sh[wid] = x;
    __syncthreads();
    if (threadIdx.x == 0) {
        int acc = 0;
        #pragma unroll
        for (int k = 0; k < 8; k++) { int t = sh[k]; sh[k] = acc; acc += t; }
        g_bsum[blockIdx.x] = acc;
    }
    __syncthreads();
    int excl = x - v + sh[wid];
    if (i < n) g_rowptr[i] = excl;
}

// finalize rowptr (+block offset) and compute norm
__global__ void k_scanC(int n, int e) {
    __shared__ int s_off;
    int t = threadIdx.x;
    int lane = t & 31;
    if (t < 32) {
        int acc = 0;
        for (int k = lane; k < blockIdx.x; k += 32) acc += g_bsum[k];
        #pragma unroll
        for (int o = 16; o > 0; o >>= 1)
            acc += __shfl_down_sync(0xffffffffu, acc, o);
        if (lane == 0) s_off = acc;
    }
    __syncthreads();
    int i = blockIdx.x * SCAN_B + t;
    if (i < n) {
        g_rowptr[i] += s_off;
        g_norm[i] = rsqrtf(fmaxf(g_deg[i], 1.0f));
        if (i == 0) g_rowptr[n] = e;
    }
}

// fused: fill CSR (blocks [0, fb)) + prep g_ha (blocks [fb, ...)).
// Also re-zeroes g_deg/g_cnt for the next graph replay (their last readers,
// scanA/scanC, already ran this launch).
__global__ void k_prepfill(const float4* __restrict__ h,
                           const int* __restrict__ src,
                           const int* __restrict__ dst,
                           const float* __restrict__ w,
                           int e, int n16, int fb) {
    if (blockIdx.x < fb) {
        int i = blockIdx.x * blockDim.x + threadIdx.x;
        if (i >= e) return;
        int pos = g_rowptr[dst[i]] + g_rank[i];
        g_edge[pos] = make_float2(__int_as_float(src[i]), w[i]);
    } else {
        int idx4 = (blockIdx.x - fb) * blockDim.x + threadIdx.x;
        if (idx4 >= n16) return;
        int node = idx4 >> 4;
        if (idx4 < NN) { g_deg[idx4] = 0.0f; g_cnt[idx4] = 0; }
        float nm = __ldg(&g_norm[node]);
        float4 v = h[idx4];
        __half2 a = __floats2half2_rn(v.x * nm, v.y * nm);
        __half2 b = __floats2half2_rn(v.z * nm, v.w * nm);
        uint2 pk = make_uint2(*reinterpret_cast<uint32_t*>(&a),
                              *reinterpret_cast<uint32_t*>(&b));
        reinterpret_cast<uint2*>(g_ha)[idx4] = pk;
    }
}

// ---------------- gather layers ----------------

// 8 lanes per node; lane sub owns dims [sub*8, sub*8+8) = one uint4 of fp16.
// LAYER=0: read g_ha; g_hb = fp16(sum * norm^2).
// LAYER=1: read g_hb; out = (h0 + hb_own/norm + sum*norm) / 3.
template <int LAYER>
__device__ __forceinline__ void acc8(float* acc, uint4 r, float wt) {
    const __half2* hp = reinterpret_cast<const __half2*>(&r);
    #pragma unroll
    for (int k = 0; k < 4; k++) {
        float2 f = __half22float2(hp[k]);
        acc[2 * k]     += f.x * wt;
        acc[2 * k + 1] += f.y * wt;
    }
}

template <int LAYER>
__global__ void k_gather(const float4* __restrict__ h4,
                         float4* __restrict__ out, int n) {
    const uint4* rows = (LAYER == 0) ? g_ha : g_hb;
    int gid = (blockIdx.x * blockDim.x + threadIdx.x) >> 3;   // node
    int sub = threadIdx.x & 7;                                 // lane in group
    if (gid >= n) return;
    int beg = g_rowptr[gid];
    int end = g_rowptr[gid + 1];

    float acc[8] = {0.f, 0.f, 0.f, 0.f, 0.f, 0.f, 0.f, 0.f};
    int j = beg;
    for (; j + 4 <= end; j += 4) {
        float2 e0 = g_edge[j],     e1 = g_edge[j + 1];
        float2 e2 = g_edge[j + 2], e3 = g_edge[j + 3];
        uint4 r0 = rows[(size_t)__float_as_int(e0.x) * 8 + sub];
        uint4 r1 = rows[(size_t)__float_as_int(e1.x) * 8 + sub];
        uint4 r2 = rows[(size_t)__float_as_int(e2.x) * 8 + sub];
        uint4 r3 = rows[(size_t)__float_as_int(e3.x) * 8 + sub];
        acc8<LAYER>(acc, r0, e0.y);
        acc8<LAYER>(acc, r1, e1.y);
        acc8<LAYER>(acc, r2, e2.y);
        acc8<LAYER>(acc, r3, e3.y);
    }
    for (; j < end; ++j) {
        float2 e = g_edge[j];
        uint4 r = rows[(size_t)__float_as_int(e.x) * 8 + sub];
        acc8<LAYER>(acc, r, e.y);
    }

    float nm = g_norm[gid];
    if (LAYER == 0) {
        float s = nm * nm;                       // h1*norm = sum*norm^2
        __half2 o0 = __floats2half2_rn(acc[0] * s, acc[1] * s);
        __half2 o1 = __floats2half2_rn(acc[2] * s, acc[3] * s);
        __half2 o2 = __floats2half2_rn(acc[4] * s, acc[5] * s);
        __half2 o3 = __floats2half2_rn(acc[6] * s, acc[7] * s);
        uint4 st = make_uint4(*reinterpret_cast<uint32_t*>(&o0),
                              *reinterpret_cast<uint32_t*>(&o1),
                              *reinterpret_cast<uint32_t*>(&o2),
                              *reinterpret_cast<uint32_t*>(&o3));
        g_hb[(size_t)gid * 8 + sub] = st;
    } else {
        float rin = __frcp_rn(nm);               // 1/norm, norm in (0,1]
        uint4 hb = g_hb[(size_t)gid * 8 + sub];
        const __half2* hp = reinterpret_cast<const __half2*>(&hb);
        float h1[8];
        #pragma unroll
        for (int k = 0; k < 4; k++) {
            float2 f = __half22float2(hp[k]);
            h1[2 * k]     = f.x * rin;
            h1[2 * k + 1] = f.y * rin;
        }
        size_t b4 = (size_t)gid * 16 + sub * 2;  // float4 index into h0/out
        float4 h0a = h4[b4], h0b = h4[b4 + 1];
        const float third = 1.0f / 3.0f;
        float4 oa, ob;
        oa.x = (h0a.x + h1[0] + acc[0] * nm) * third;
        oa.y = (h0a.y + h1[1] + acc[1] * nm) * third;
        oa.z = (h0a.z + h1[2] + acc[2] * nm) * third;
        oa.w = (h0a.w + h1[3] + acc[3] * nm) * third;
        ob.x = (h0b.x + h1[4] + acc[4] * nm) * third;
        ob.y = (h0b.y + h1[5] + acc[5] * nm) * third;
        ob.z = (h0b.z + h1[6] + acc[6] * nm) * third;
        ob.w = (h0b.w + h1[7] + acc[7] * nm) * third;
        out[b4] = oa;
        out[b4 + 1] = ob;
    }
}

extern "C" void kernel_launch(void* const* d_in, const int* in_sizes, int n_in,
                              void* d_out, int out_size) {
    const float* h   = (const float*)d_in[0];
    const float* w   = (const float*)d_in[1];
    const int*   src = (const int*)d_in[2];
    const int*   dst = (const int*)d_in[3];
    float* out = (float*)d_out;

    const int N   = in_sizes[0] / 64;   // 100000
    const int E   = in_sizes[1];        // 1600000
    const int B   = 256;
    const int nb  = (N + SCAN_B - 1) / SCAN_B;   // 391
    const int N16 = N * 16;
    const int fb  = (E + B - 1) / B;             // fill blocks
    const int pb  = (N16 + B - 1) / B;           // prep blocks

    k_hist    <<<(E + B - 1) / B, B>>>(w, dst, E);
    k_scanA   <<<nb, SCAN_B>>>(N);
    k_scanC   <<<nb, SCAN_B>>>(N, E);
    k_prepfill<<<fb + pb, B>>>((const float4*)h, src, dst, w, E, N16, fb);

    const int ggrid = (N * 8 + B - 1) / B;       // 8 lanes per node
    k_gather<0><<<ggrid, B>>>((const float4*)h, (float4*)out, N);
    k_gather<1><<<ggrid, B>>>((const float4*)h, (float4*)out, N);
}